// round 3
// baseline (speedup 1.0000x reference)
#include <cuda_runtime.h>

// Problem constants: B=2, H=16, T=8192, D=64, M=8
#define TT 8192
#define BB 2
#define HH 16
#define DD 64
#define MM 8

#define THREADS 128          // 4 warps, 8 lanes per row -> 16 rows per pass
#define PASSES 16            // 256 rows per block
#define ROWS_PER_BLOCK (PASSES * (THREADS / 8))   // 256

// cos/sin table: per t, 32 pairs (cos, sin) interleaved -> 64 floats per t. 2 MB.
__device__ float g_tab[TT * DD];

// ---------------------------------------------------------------------------
// Prep kernel: accurate sincosf into the table (full-range reduction, ~2 ulp)
// ---------------------------------------------------------------------------
__global__ void build_table_kernel(const float* __restrict__ pos,
                                   const float* __restrict__ freq) {
    int idx = blockIdx.x * blockDim.x + threadIdx.x;   // t*32 + j
    if (idx >= TT * 32) return;
    int t = idx >> 5;
    int j = idx & 31;
    float a = pos[t] * freq[j];
    float s, c;
    sincosf(a, &s, &c);
    g_tab[t * DD + 2 * j]     = c;
    g_tab[t * DD + 2 * j + 1] = s;
}

// ---------------------------------------------------------------------------
// Main kernel: Householder stack (reverse) + RoPE, 8 lanes per row
// ---------------------------------------------------------------------------
__global__ void __launch_bounds__(THREADS)
hh_rope_kernel(const float* __restrict__ q,
               const float* __restrict__ k,
               const float* __restrict__ V,
               float* __restrict__ out) {
    const int bh   = blockIdx.y;          // b*H + h   (0..31)
    const int h    = bh & (HH - 1);
    const int tsel = blockIdx.z;          // 0 = q, 1 = k
    const int t0   = blockIdx.x * ROWS_PER_BLOCK;

    const int tid   = threadIdx.x;
    const int lane8 = tid & 7;            // which 8-float chunk of the row

    // ---- compute 1/||V[h][m]|| (once per block) ----
    __shared__ float s_rnorm[MM];
    if (tid < MM) {
        const float* vp = V + ((size_t)h * MM + tid) * DD;
        float sum = 0.f;
        #pragma unroll
        for (int d = 0; d < DD; d++) sum = fmaf(vp[d], vp[d], sum);
        s_rnorm[tid] = rsqrtf(sum + 1e-16f);   // EPS^2, EPS = 1e-8
    }
    __syncthreads();

    // ---- preload this lane's slice of all 8 unit reflectors into registers ----
    float4 vA[MM], vB[MM];
    {
        const float4* Vp = (const float4*)(V + (size_t)h * MM * DD);
        #pragma unroll
        for (int m = 0; m < MM; m++) {
            float r  = s_rnorm[m];
            float4 a = Vp[m * 16 + lane8 * 2];
            float4 b = Vp[m * 16 + lane8 * 2 + 1];
            vA[m] = make_float4(a.x * r, a.y * r, a.z * r, a.w * r);
            vB[m] = make_float4(b.x * r, b.y * r, b.z * r, b.w * r);
        }
    }

    const float* src = (tsel ? k : q) + ((size_t)bh * TT + t0) * DD;
    float*       dst = out + ((size_t)tsel * BB * HH * TT + (size_t)bh * TT + t0) * DD;
    const float4* src4 = (const float4*)src;
    float4*       dst4 = (float4*)dst;
    const float4* tab4 = (const float4*)(g_tab) + (size_t)t0 * 16;  // 16 float4 per t

    for (int p = 0; p < PASSES; p++) {
        const int f = (p * THREADS + tid) * 2;   // float4 index (coalesced)

        float4 z0 = src4[f];
        float4 z1 = src4[f + 1];
        float4 c0 = tab4[f];        // (cos,sin,cos,sin) for pairs 0,1 of this chunk
        float4 c1 = tab4[f + 1];    // pairs 2,3

        // ---- 8 Householder reflections, m = 7 .. 0 ----
        #pragma unroll
        for (int m = MM - 1; m >= 0; m--) {
            float d0 =          z0.x * vA[m].x;
            d0 = fmaf(z0.y, vA[m].y, d0);
            d0 = fmaf(z0.z, vA[m].z, d0);
            d0 = fmaf(z0.w, vA[m].w, d0);
            d0 = fmaf(z1.x, vB[m].x, d0);
            d0 = fmaf(z1.y, vB[m].y, d0);
            d0 = fmaf(z1.z, vB[m].z, d0);
            d0 = fmaf(z1.w, vB[m].w, d0);
            d0 += __shfl_xor_sync(0xffffffffu, d0, 1);
            d0 += __shfl_xor_sync(0xffffffffu, d0, 2);
            d0 += __shfl_xor_sync(0xffffffffu, d0, 4);
            const float s = -2.0f * d0;
            z0.x = fmaf(s, vA[m].x, z0.x);
            z0.y = fmaf(s, vA[m].y, z0.y);
            z0.z = fmaf(s, vA[m].z, z0.z);
            z0.w = fmaf(s, vA[m].w, z0.w);
            z1.x = fmaf(s, vB[m].x, z1.x);
            z1.y = fmaf(s, vB[m].y, z1.y);
            z1.z = fmaf(s, vB[m].z, z1.z);
            z1.w = fmaf(s, vB[m].w, z1.w);
        }

        // ---- RoPE rotate: pairs (x,y) and (z,w), table holds (cos,sin) per pair
        float4 o0, o1;
        o0.x = z0.x * c0.x - z0.y * c0.y;
        o0.y = fmaf(z0.x, c0.y, z0.y * c0.x);
        o0.z = z0.z * c0.z - z0.w * c0.w;
        o0.w = fmaf(z0.z, c0.w, z0.w * c0.z);
        o1.x = z1.x * c1.x - z1.y * c1.y;
        o1.y = fmaf(z1.x, c1.y, z1.y * c1.x);
        o1.z = z1.z * c1.z - z1.w * c1.w;
        o1.w = fmaf(z1.z, c1.w, z1.w * c1.z);

        dst4[f]     = o0;
        dst4[f + 1] = o1;
    }
}

// ---------------------------------------------------------------------------
// Launch
// ---------------------------------------------------------------------------
extern "C" void kernel_launch(void* const* d_in, const int* in_sizes, int n_in,
                              void* d_out, int out_size) {
    const float* q    = (const float*)d_in[0];
    const float* k    = (const float*)d_in[1];
    const float* V    = (const float*)d_in[2];
    const float* pos  = (const float*)d_in[3];
    const float* freq = (const float*)d_in[4];
    float* out = (float*)d_out;

    // 1) cos/sin table (accurate, one pass, lives in L2 thereafter)
    {
        int n = TT * 32;
        build_table_kernel<<<(n + 255) / 256, 256>>>(pos, freq);
    }

    // 2) main fused kernel: grid = (t-chunks, b*h, q/k)
    dim3 grid(TT / ROWS_PER_BLOCK, BB * HH, 2);   // (32, 32, 2)
    hh_rope_kernel<<<grid, THREADS>>>(q, k, V, out);
}